// round 2
// baseline (speedup 1.0000x reference)
#include <cuda_runtime.h>

// Problem constants
#define BATCH   4
#define HEADS   16
#define SEQ     2048
#define DK      64
#define DMODEL  1024
#define NTOK    (BATCH * SEQ)            // 8192
#define BH      (BATCH * HEADS)          // 64
#define CSTRIDE ((size_t)BH * SEQ * DK)  // 8388608 floats per Q/K/V plane

// Scratch (device globals: cudaMalloc is forbidden)
__device__ float g_qkv[3 * BH * SEQ * DK];   // [c][b*H+h][s][dk]  (96 MB)
__device__ float g_heads[NTOK * DMODEL];     // [b*S+s][h*DK+dk]   (32 MB)

// ---------------------------------------------------------------------------
// SGEMM C = A * B^T.  A: [M,K] row-major, B: [N,K] row-major.
// 128x128 block tile, BK=8, 256 threads, 8x8 per-thread register tile.
// mode 0: plain store to C.
// mode 1: scatter columns e=(c,h,dk) of QKV into g_qkv planes.
// ---------------------------------------------------------------------------
__global__ __launch_bounds__(256)
void sgemm_nt_kernel(const float* __restrict__ A, const float* __restrict__ B,
                     float* __restrict__ C, int M, int N, int K, int mode)
{
    __shared__ float As[8][128];
    __shared__ float Bs[8][128];

    const int tid = threadIdx.x;
    const int tx  = tid & 15;
    const int ty  = tid >> 4;
    const int m0  = blockIdx.y * 128;
    const int n0  = blockIdx.x * 128;

    const int lr = tid >> 1;          // 0..127 row within tile
    const int lc = (tid & 1) * 4;     // 0 or 4, k-quad

    const float* Ag = A + (size_t)(m0 + lr) * K + lc;
    const float* Bg = B + (size_t)(n0 + lr) * K + lc;

    float4 av = *(const float4*)Ag;
    float4 bv = *(const float4*)Bg;

    float acc[8][8];
#pragma unroll
    for (int i = 0; i < 8; ++i)
#pragma unroll
        for (int j = 0; j < 8; ++j) acc[i][j] = 0.0f;

    const int nk = K >> 3;
    for (int kt = 0; kt < nk; ++kt) {
        As[lc + 0][lr] = av.x;
        As[lc + 1][lr] = av.y;
        As[lc + 2][lr] = av.z;
        As[lc + 3][lr] = av.w;
        Bs[lc + 0][lr] = bv.x;
        Bs[lc + 1][lr] = bv.y;
        Bs[lc + 2][lr] = bv.z;
        Bs[lc + 3][lr] = bv.w;
        __syncthreads();

        if (kt + 1 < nk) {            // prefetch next k-slab while computing
            av = *(const float4*)(Ag + (size_t)(kt + 1) * 8);
            bv = *(const float4*)(Bg + (size_t)(kt + 1) * 8);
        }

#pragma unroll
        for (int kk = 0; kk < 8; ++kk) {
            float4 a0 = *(const float4*)&As[kk][ty * 8];
            float4 a1 = *(const float4*)&As[kk][ty * 8 + 4];
            float4 b0 = *(const float4*)&Bs[kk][tx * 8];
            float4 b1 = *(const float4*)&Bs[kk][tx * 8 + 4];
            float a[8] = {a0.x, a0.y, a0.z, a0.w, a1.x, a1.y, a1.z, a1.w};
            float b[8] = {b0.x, b0.y, b0.z, b0.w, b1.x, b1.y, b1.z, b1.w};
#pragma unroll
            for (int i = 0; i < 8; ++i)
#pragma unroll
                for (int j = 0; j < 8; ++j)
                    acc[i][j] += a[i] * b[j];
        }
        __syncthreads();
    }

    if (mode == 0) {
#pragma unroll
        for (int i = 0; i < 8; ++i) {
            float* cr = C + (size_t)(m0 + ty * 8 + i) * N + n0 + tx * 8;
            *(float4*)(cr)     = make_float4(acc[i][0], acc[i][1], acc[i][2], acc[i][3]);
            *(float4*)(cr + 4) = make_float4(acc[i][4], acc[i][5], acc[i][6], acc[i][7]);
        }
    } else {
        // column index e = c*1024 + h*64 + dk ; an 8-wide, 8-aligned column
        // group never crosses an (c,h) boundary.
        const int nb  = n0 + tx * 8;
        const int c   = nb >> 10;
        const int h   = (nb >> 6) & (HEADS - 1);
        const int dk0 = nb & (DK - 1);
#pragma unroll
        for (int i = 0; i < 8; ++i) {
            const int m = m0 + ty * 8 + i;
            const int b = m >> 11;           // m / SEQ
            const int s = m & (SEQ - 1);
            float* dst = g_qkv + (size_t)c * CSTRIDE
                       + ((size_t)(b * HEADS + h) * SEQ + s) * DK + dk0;
            *(float4*)(dst)     = make_float4(acc[i][0], acc[i][1], acc[i][2], acc[i][3]);
            *(float4*)(dst + 4) = make_float4(acc[i][4], acc[i][5], acc[i][6], acc[i][7]);
        }
    }
}

// ---------------------------------------------------------------------------
// Causal flash attention, fp32.
// Grid: (SEQ/64, BH). Block: 256 threads = 16x16.
// Q tile 64 queries x 64 dk (scaled by 1/8 on load), key tiles of 32.
// Per thread: S sub-tile 4x2 (q x k), O sub-tile 4x4 (q x dk).
// ---------------------------------------------------------------------------
__global__ __launch_bounds__(256)
void attn_kernel()
{
    __shared__ float Qs[64][64];       // [q][d]   natural
    __shared__ float KsT[64][34];      // [d][k]   transposed (+pad)
    __shared__ float Vs[32][64];       // [k][d]   natural
    __shared__ float Ps[64][32];       // [q][k]   natural

    const int tid = threadIdx.x;
    const int tx  = tid & 15;
    const int ty  = tid >> 4;
    const int qt  = blockIdx.x;        // query tile (0..31)
    const int bh  = blockIdx.y;        // b*H + h   (0..63)
    const int q0  = qt * 64;

    const float* Qg = g_qkv + ((size_t)bh * SEQ + q0) * DK;
    const float* Kg = g_qkv + CSTRIDE     + (size_t)bh * SEQ * DK;
    const float* Vg = g_qkv + 2 * CSTRIDE + (size_t)bh * SEQ * DK;

    // Load Q tile (64x64 floats, 4 float4 per thread), pre-scaled by 1/sqrt(DK)
#pragma unroll
    for (int it = 0; it < 4; ++it) {
        int idx4 = tid + it * 256;
        int r  = idx4 >> 4;
        int d4 = (idx4 & 15) * 4;
        float4 v = *(const float4*)(Qg + (size_t)r * DK + d4);
        Qs[r][d4 + 0] = v.x * 0.125f;
        Qs[r][d4 + 1] = v.y * 0.125f;
        Qs[r][d4 + 2] = v.z * 0.125f;
        Qs[r][d4 + 3] = v.w * 0.125f;
    }

    float m_[4], l_[4], acc[4][4];
#pragma unroll
    for (int i = 0; i < 4; ++i) {
        m_[i] = -1e30f;
        l_[i] = 0.0f;
#pragma unroll
        for (int j = 0; j < 4; ++j) acc[i][j] = 0.0f;
    }

    const int nkt = 2 * qt + 2;        // 32-key tiles up to (and incl.) diagonal
    for (int kt = 0; kt < nkt; ++kt) {
        __syncthreads();               // previous iteration fully consumed smem
        const int k0 = kt * 32;

        // Load K (transposed into KsT) and V (natural), 2 float4 each
#pragma unroll
        for (int it = 0; it < 2; ++it) {
            int idx4 = tid + it * 256;
            int r  = idx4 >> 4;        // key row 0..31
            int d4 = (idx4 & 15) * 4;
            float4 kv = *(const float4*)(Kg + (size_t)(k0 + r) * DK + d4);
            KsT[d4 + 0][r] = kv.x;
            KsT[d4 + 1][r] = kv.y;
            KsT[d4 + 2][r] = kv.z;
            KsT[d4 + 3][r] = kv.w;
            float4 vv = *(const float4*)(Vg + (size_t)(k0 + r) * DK + d4);
            *(float4*)&Vs[r][d4] = vv;
        }
        __syncthreads();

        // S = Q K^T  (4x2 per thread), reduction over d (uniform -> broadcast)
        float s[4][2];
        s[0][0] = s[0][1] = s[1][0] = s[1][1] = 0.0f;
        s[2][0] = s[2][1] = s[3][0] = s[3][1] = 0.0f;
#pragma unroll 8
        for (int d = 0; d < 64; ++d) {
            float2 bk = *(const float2*)&KsT[d][tx * 2];
            float aq0 = Qs[ty * 4 + 0][d];
            float aq1 = Qs[ty * 4 + 1][d];
            float aq2 = Qs[ty * 4 + 2][d];
            float aq3 = Qs[ty * 4 + 3][d];
            s[0][0] += aq0 * bk.x;  s[0][1] += aq0 * bk.y;
            s[1][0] += aq1 * bk.x;  s[1][1] += aq1 * bk.y;
            s[2][0] += aq2 * bk.x;  s[2][1] += aq2 * bk.y;
            s[3][0] += aq3 * bk.x;  s[3][1] += aq3 * bk.y;
        }

        // Causal mask (only tiles touching/above the diagonal need it)
        if (kt >= 2 * qt) {
#pragma unroll
            for (int i = 0; i < 4; ++i) {
                const int qg = q0 + ty * 4 + i;
#pragma unroll
                for (int j = 0; j < 2; ++j) {
                    const int kg = k0 + tx * 2 + j;
                    if (kg > qg) s[i][j] = -1e30f;
                }
            }
        }

        // Online softmax per query row (row group = 16 lanes sharing ty)
#pragma unroll
        for (int i = 0; i < 4; ++i) {
            float mx = fmaxf(s[i][0], s[i][1]);
            mx = fmaxf(mx, __shfl_xor_sync(0xffffffffu, mx, 8));
            mx = fmaxf(mx, __shfl_xor_sync(0xffffffffu, mx, 4));
            mx = fmaxf(mx, __shfl_xor_sync(0xffffffffu, mx, 2));
            mx = fmaxf(mx, __shfl_xor_sync(0xffffffffu, mx, 1));
            const float mnew = fmaxf(m_[i], mx);
            const float p0 = __expf(s[i][0] - mnew);
            const float p1 = __expf(s[i][1] - mnew);
            float rs = p0 + p1;
            rs += __shfl_xor_sync(0xffffffffu, rs, 8);
            rs += __shfl_xor_sync(0xffffffffu, rs, 4);
            rs += __shfl_xor_sync(0xffffffffu, rs, 2);
            rs += __shfl_xor_sync(0xffffffffu, rs, 1);
            const float f = __expf(m_[i] - mnew);
            l_[i] = l_[i] * f + rs;
            m_[i] = mnew;
            acc[i][0] *= f; acc[i][1] *= f; acc[i][2] *= f; acc[i][3] *= f;
            *(float2*)&Ps[ty * 4 + i][tx * 2] = make_float2(p0, p1);
        }
        __syncthreads();

        // O += P V  (4x4 per thread), reduction over k (uniform -> broadcast)
#pragma unroll 8
        for (int k = 0; k < 32; ++k) {
            float4 vv = *(const float4*)&Vs[k][tx * 4];
            float p0 = Ps[ty * 4 + 0][k];
            float p1 = Ps[ty * 4 + 1][k];
            float p2 = Ps[ty * 4 + 2][k];
            float p3 = Ps[ty * 4 + 3][k];
            acc[0][0] += p0 * vv.x; acc[0][1] += p0 * vv.y; acc[0][2] += p0 * vv.z; acc[0][3] += p0 * vv.w;
            acc[1][0] += p1 * vv.x; acc[1][1] += p1 * vv.y; acc[1][2] += p1 * vv.z; acc[1][3] += p1 * vv.w;
            acc[2][0] += p2 * vv.x; acc[2][1] += p2 * vv.y; acc[2][2] += p2 * vv.z; acc[2][3] += p2 * vv.w;
            acc[3][0] += p3 * vv.x; acc[3][1] += p3 * vv.y; acc[3][2] += p3 * vv.z; acc[3][3] += p3 * vv.w;
        }
    }

    // Normalize + store to heads scratch [b*S+s][h*DK+dk]
    const int b = bh >> 4;
    const int h = bh & 15;
#pragma unroll
    for (int i = 0; i < 4; ++i) {
        const float inv = 1.0f / l_[i];
        float* dst = g_heads + ((size_t)(b * SEQ + q0 + ty * 4 + i)) * DMODEL
                   + h * DK + tx * 4;
        *(float4*)dst = make_float4(acc[i][0] * inv, acc[i][1] * inv,
                                    acc[i][2] * inv, acc[i][3] * inv);
    }
}

// ---------------------------------------------------------------------------
extern "C" void kernel_launch(void* const* d_in, const int* in_sizes, int n_in,
                              void* d_out, int out_size)
{
    const float* x     = (const float*)d_in[0];   // [4,2048,1024]
    const float* w_qkv = (const float*)d_in[1];   // [3072,1024]
    const float* w_o   = (const float*)d_in[2];   // [1024,1024]
    float* out = (float*)d_out;                   // [4,2048,1024]

    float* heads_ptr = nullptr;
    cudaGetSymbolAddress((void**)&heads_ptr, g_heads);

    dim3 blk(256);
    // 1) QKV projection, scattered into per-head planes
    sgemm_nt_kernel<<<dim3(24, 64), blk>>>(x, w_qkv, nullptr,
                                           NTOK, 3 * DMODEL, DMODEL, 1);
    // 2) causal attention -> heads scratch
    attn_kernel<<<dim3(SEQ / 64, BH), blk>>>();
    // 3) output projection
    sgemm_nt_kernel<<<dim3(8, 64), blk>>>(heads_ptr, w_o, out,
                                          NTOK, DMODEL, DMODEL, 0);
}

// round 4
// speedup vs baseline: 1.4486x; 1.4486x over previous
#include <cuda_runtime.h>
#include <cuda_bf16.h>
#include <stdint.h>

// Problem constants
#define BATCH   4
#define HEADS   16
#define SEQ     2048
#define DK      64
#define DMODEL  1024
#define NTOK    (BATCH * SEQ)            // 8192
#define BH      (BATCH * HEADS)          // 64
#define CSTRIDE ((size_t)BH * SEQ * DK)  // floats per Q/K/V plane

// Scratch (device globals: cudaMalloc is forbidden)
__device__ float         g_qkv[3 * BH * SEQ * DK];       // fp32 [c][b*H+h][s][dk]
__device__ __nv_bfloat16 g_xhi[NTOK * DMODEL];
__device__ __nv_bfloat16 g_xlo[NTOK * DMODEL];
__device__ __nv_bfloat16 g_wqhi[3 * DMODEL * DMODEL];
__device__ __nv_bfloat16 g_wqlo[3 * DMODEL * DMODEL];
__device__ __nv_bfloat16 g_hhi[NTOK * DMODEL];           // attention output hi
__device__ __nv_bfloat16 g_hlo[NTOK * DMODEL];           // attention output lo
__device__ __nv_bfloat16 g_wohi[DMODEL * DMODEL];
__device__ __nv_bfloat16 g_wolo[DMODEL * DMODEL];

// ---------------------------------------------------------------------------
// Warp MMA helpers (sm_80+ instructions only — no arch-feature suffix needed)
// ---------------------------------------------------------------------------
__device__ __forceinline__ uint32_t smem_u32(const void* p) {
    uint32_t a;
    asm("{ .reg .u64 t; cvta.to.shared.u64 t, %1; cvt.u32.u64 %0, t; }"
        : "=r"(a) : "l"(p));
    return a;
}
__device__ __forceinline__ void ldsm_x4(uint32_t& r0, uint32_t& r1,
                                        uint32_t& r2, uint32_t& r3, uint32_t addr) {
    asm volatile("ldmatrix.sync.aligned.m8n8.x4.shared.b16 {%0,%1,%2,%3}, [%4];"
                 : "=r"(r0), "=r"(r1), "=r"(r2), "=r"(r3) : "r"(addr));
}
__device__ __forceinline__ void ldsm_x2(uint32_t& r0, uint32_t& r1, uint32_t addr) {
    asm volatile("ldmatrix.sync.aligned.m8n8.x2.shared.b16 {%0,%1}, [%2];"
                 : "=r"(r0), "=r"(r1) : "r"(addr));
}
__device__ __forceinline__ void mma_bf16(float* c, const uint32_t* a, const uint32_t* b) {
    asm volatile("mma.sync.aligned.m16n8k16.row.col.f32.bf16.bf16.f32 "
                 "{%0,%1,%2,%3}, {%4,%5,%6,%7}, {%8,%9}, {%0,%1,%2,%3};"
                 : "+f"(c[0]), "+f"(c[1]), "+f"(c[2]), "+f"(c[3])
                 : "r"(a[0]), "r"(a[1]), "r"(a[2]), "r"(a[3]),
                   "r"(b[0]), "r"(b[1]));
}

// ---------------------------------------------------------------------------
// fp32 -> bf16 hi/lo split (hi = rn(x), lo = rn(x - hi))
// ---------------------------------------------------------------------------
__global__ __launch_bounds__(256)
void split_kernel(const float4* __restrict__ src,
                  __nv_bfloat16* __restrict__ hi,
                  __nv_bfloat16* __restrict__ lo, int n4)
{
    int i = blockIdx.x * blockDim.x + threadIdx.x;
    if (i >= n4) return;
    float4 v = src[i];
    float f[4] = {v.x, v.y, v.z, v.w};
    __nv_bfloat16 h[4], l[4];
#pragma unroll
    for (int j = 0; j < 4; ++j) {
        h[j] = __float2bfloat16_rn(f[j]);
        l[j] = __float2bfloat16_rn(f[j] - __bfloat162float(h[j]));
    }
    __nv_bfloat162 h01; h01.x = h[0]; h01.y = h[1];
    __nv_bfloat162 h23; h23.x = h[2]; h23.y = h[3];
    __nv_bfloat162 l01; l01.x = l[0]; l01.y = l[1];
    __nv_bfloat162 l23; l23.x = l[2]; l23.y = l[3];
    *(__nv_bfloat162*)(hi + 4 * (size_t)i)     = h01;
    *(__nv_bfloat162*)(hi + 4 * (size_t)i + 2) = h23;
    *(__nv_bfloat162*)(lo + 4 * (size_t)i)     = l01;
    *(__nv_bfloat162*)(lo + 4 * (size_t)i + 2) = l23;
}

// ---------------------------------------------------------------------------
// Split-bf16 GEMM on HMMA (mma.sync):  C[M,N] = A[M,K] * B[N,K]^T, K = 1024.
// Block tile 128x128, BK=32, 256 threads = 8 warps (2m x 4n), warp tile 64x32.
// Per k16 step: 16 tile-MMAs x 3 terms (AhBh + AhBl + AlBh), fp32 accum.
// Smem rows padded to 40 bf16 (80 B) -> conflict-free ldmatrix.
// mode 0: plain store to C[M,N].  mode 1: scatter to g_qkv planes.
// ---------------------------------------------------------------------------
#define BKS      32
#define NKI      (DMODEL / BKS)         // 32
#define PSTRIDE  40                     // padded row stride (elements)
#define PLANE_B  (128 * PSTRIDE * 2)    // 10240 bytes per plane tile
#define STAGE_B4 (4 * PLANE_B)          // Ah, Al, Bh, Bl
#define GSMEM    (2 * STAGE_B4)         // 81920 bytes

__global__ __launch_bounds__(256, 1)
void gemm_mma_kernel(const __nv_bfloat16* __restrict__ Ahi,
                     const __nv_bfloat16* __restrict__ Alo,
                     const __nv_bfloat16* __restrict__ Bhi,
                     const __nv_bfloat16* __restrict__ Blo,
                     float* __restrict__ C, int N, int mode)
{
    extern __shared__ char smem[];
    const uint32_t sbase = smem_u32(smem);
    const int tid  = threadIdx.x;
    const int wid  = tid >> 5;
    const int lane = tid & 31;
    const int wm   = wid >> 2;      // 0..1  (64-row slab)
    const int wn   = wid & 3;       // 0..3  (32-col slab)
    const int m0   = blockIdx.y * 128;
    const int n0   = blockIdx.x * 128;
    const int K    = DMODEL;

    const __nv_bfloat16* gsrc[4] = {
        Ahi + (size_t)m0 * K, Alo + (size_t)m0 * K,
        Bhi + (size_t)n0 * K, Blo + (size_t)n0 * K };

    const int lrow = tid >> 2;      // 0..63 -> doubled to 128 via t loop
    const int lc16 = tid & 3;       // 16B chunk within 64B row

    // Stage-0 fill
#pragma unroll
    for (int p = 0; p < 4; ++p)
#pragma unroll
        for (int t = 0; t < 2; ++t) {
            const int idx = tid + t * 256;
            const int r = idx >> 2, c = idx & 3;
            uint4 v = *(const uint4*)(gsrc[p] + (size_t)r * K + c * 8);
            *(uint4*)(smem + p * PLANE_B + r * 80 + c * 16) = v;
        }
    __syncthreads();

    float acc[4][4][4];
#pragma unroll
    for (int mi = 0; mi < 4; ++mi)
#pragma unroll
        for (int nj = 0; nj < 4; ++nj)
#pragma unroll
            for (int q = 0; q < 4; ++q) acc[mi][nj][q] = 0.0f;

    for (int kt = 0; kt < NKI; ++kt) {
        // Prefetch next k-slab (global -> regs)
        uint4 pf[8];
        if (kt + 1 < NKI) {
            const int kc = (kt + 1) * BKS;
#pragma unroll
            for (int p = 0; p < 4; ++p)
#pragma unroll
                for (int t = 0; t < 2; ++t) {
                    const int idx = tid + t * 256;
                    const int r = idx >> 2, c = idx & 3;
                    pf[p * 2 + t] = *(const uint4*)(gsrc[p] + (size_t)r * K + kc + c * 8);
                }
        }

        // Compute current stage: 2 k16 steps
        const uint32_t sb = sbase + (kt & 1) * STAGE_B4;
#pragma unroll
        for (int ks = 0; ks < 2; ++ks) {
            uint32_t ah[4][4], al[4][4], bh[4][2], bl[4][2];
#pragma unroll
            for (int mi = 0; mi < 4; ++mi) {
                const int row = wm * 64 + mi * 16 + (lane & 15);
                const uint32_t a = sb + row * 80 + ks * 32 + (lane >> 4) * 16;
                ldsm_x4(ah[mi][0], ah[mi][1], ah[mi][2], ah[mi][3], a);
                ldsm_x4(al[mi][0], al[mi][1], al[mi][2], al[mi][3], a + PLANE_B);
            }
#pragma unroll
            for (int nj = 0; nj < 4; ++nj) {
                const int row = wn * 32 + nj * 8 + (lane & 7);
                const uint32_t a = sb + 2 * PLANE_B + row * 80
                                 + ks * 32 + ((lane >> 3) & 1) * 16;
                ldsm_x2(bh[nj][0], bh[nj][1], a);
                ldsm_x2(bl[nj][0], bl[nj][1], a + PLANE_B);
            }
#pragma unroll
            for (int mi = 0; mi < 4; ++mi)
#pragma unroll
                for (int nj = 0; nj < 4; ++nj) {
                    mma_bf16(acc[mi][nj], ah[mi], bh[nj]);
                    mma_bf16(acc[mi][nj], ah[mi], bl[nj]);
                    mma_bf16(acc[mi][nj], al[mi], bh[nj]);
                }
        }

        if (kt + 1 < NKI) {
            __syncthreads();     // all warps done reading the other stage
            char* dst = smem + ((kt + 1) & 1) * STAGE_B4;
#pragma unroll
            for (int p = 0; p < 4; ++p)
#pragma unroll
                for (int t = 0; t < 2; ++t) {
                    const int idx = tid + t * 256;
                    const int r = idx >> 2, c = idx & 3;
                    *(uint4*)(dst + p * PLANE_B + r * 80 + c * 16) = pf[p * 2 + t];
                }
            __syncthreads();
        }
    }
    (void)lrow; (void)lc16;

    // Epilogue. Fragment layout: c0,c1 -> row=lane>>2, cols=(lane&3)*2 +{0,1};
    // c2,c3 -> row+8.
#pragma unroll
    for (int mi = 0; mi < 4; ++mi)
#pragma unroll
        for (int nj = 0; nj < 4; ++nj) {
            const int mrow = m0 + wm * 64 + mi * 16 + (lane >> 2);
            const int ncol = n0 + wn * 32 + nj * 8 + (lane & 3) * 2;
            if (mode == 0) {
                *(float2*)(C + (size_t)mrow * N + ncol) =
                    make_float2(acc[mi][nj][0], acc[mi][nj][1]);
                *(float2*)(C + (size_t)(mrow + 8) * N + ncol) =
                    make_float2(acc[mi][nj][2], acc[mi][nj][3]);
            } else {
                const int cc = ncol >> 10;
                const int h  = (ncol >> 6) & (HEADS - 1);
                const int dk = ncol & (DK - 1);
#pragma unroll
                for (int half = 0; half < 2; ++half) {
                    const int m = mrow + half * 8;
                    const int b = m >> 11;
                    const int s = m & (SEQ - 1);
                    float* dst = g_qkv + (size_t)cc * CSTRIDE
                               + ((size_t)(b * HEADS + h) * SEQ + s) * DK + dk;
                    *(float2*)dst = make_float2(acc[mi][nj][half * 2],
                                                acc[mi][nj][half * 2 + 1]);
                }
            }
        }
}

// ---------------------------------------------------------------------------
// Causal flash attention, fp32; epilogue emits bf16 hi/lo heads.
// Grid: (SEQ/64, BH). Block: 256 threads = 16x16.
// ---------------------------------------------------------------------------
__global__ __launch_bounds__(256)
void attn_kernel()
{
    __shared__ float Qs[64][64];
    __shared__ float KsT[64][34];
    __shared__ float Vs[32][64];
    __shared__ float Ps[64][32];

    const int tid = threadIdx.x;
    const int tx  = tid & 15;
    const int ty  = tid >> 4;
    const int qt  = blockIdx.x;
    const int bh  = blockIdx.y;
    const int q0  = qt * 64;

    const float* Qg = g_qkv + ((size_t)bh * SEQ + q0) * DK;
    const float* Kg = g_qkv + CSTRIDE     + (size_t)bh * SEQ * DK;
    const float* Vg = g_qkv + 2 * CSTRIDE + (size_t)bh * SEQ * DK;

#pragma unroll
    for (int it = 0; it < 4; ++it) {
        int idx4 = tid + it * 256;
        int r  = idx4 >> 4;
        int d4 = (idx4 & 15) * 4;
        float4 v = *(const float4*)(Qg + (size_t)r * DK + d4);
        Qs[r][d4 + 0] = v.x * 0.125f;
        Qs[r][d4 + 1] = v.y * 0.125f;
        Qs[r][d4 + 2] = v.z * 0.125f;
        Qs[r][d4 + 3] = v.w * 0.125f;
    }

    float m_[4], l_[4], acc[4][4];
#pragma unroll
    for (int i = 0; i < 4; ++i) {
        m_[i] = -1e30f; l_[i] = 0.0f;
#pragma unroll
        for (int j = 0; j < 4; ++j) acc[i][j] = 0.0f;
    }

    const int nkt = 2 * qt + 2;
    for (int kt = 0; kt < nkt; ++kt) {
        __syncthreads();
        const int k0 = kt * 32;
#pragma unroll
        for (int it = 0; it < 2; ++it) {
            int idx4 = tid + it * 256;
            int r  = idx4 >> 4;
            int d4 = (idx4 & 15) * 4;
            float4 kv = *(const float4*)(Kg + (size_t)(k0 + r) * DK + d4);
            KsT[d4 + 0][r] = kv.x;
            KsT[d4 + 1][r] = kv.y;
            KsT[d4 + 2][r] = kv.z;
            KsT[d4 + 3][r] = kv.w;
            float4 vv = *(const float4*)(Vg + (size_t)(k0 + r) * DK + d4);
            *(float4*)&Vs[r][d4] = vv;
        }
        __syncthreads();

        float s[4][2];
        s[0][0] = s[0][1] = s[1][0] = s[1][1] = 0.0f;
        s[2][0] = s[2][1] = s[3][0] = s[3][1] = 0.0f;
#pragma unroll 8
        for (int d = 0; d < 64; ++d) {
            float2 bk = *(const float2*)&KsT[d][tx * 2];
            float aq0 = Qs[ty * 4 + 0][d];
            float aq1 = Qs[ty * 4 + 1][d];
            float aq2 = Qs[ty * 4 + 2][d];
            float aq3 = Qs[ty * 4 + 3][d];
            s[0][0] += aq0 * bk.x;  s[0][1] += aq0 * bk.y;
            s[1][0] += aq1 * bk.x;  s[1][1] += aq1 * bk.y;
            s[2][0] += aq2 * bk.x;  s[2][1] += aq2 * bk.y;
            s[3][0] += aq3 * bk.x;  s[3][1] += aq3 * bk.y;
        }

        if (kt >= 2 * qt) {
#pragma unroll
            for (int i = 0; i < 4; ++i) {
                const int qg = q0 + ty * 4 + i;
#pragma unroll
                for (int j = 0; j < 2; ++j) {
                    const int kg = k0 + tx * 2 + j;
                    if (kg > qg) s[i][j] = -1e30f;
                }
            }
        }

#pragma unroll
        for (int i = 0; i < 4; ++i) {
            float mx = fmaxf(s[i][0], s[i][1]);
            mx = fmaxf(mx, __shfl_xor_sync(0xffffffffu, mx, 8));
            mx = fmaxf(mx, __shfl_xor_sync(0xffffffffu, mx, 4));
            mx = fmaxf(mx, __shfl_xor_sync(0xffffffffu, mx, 2));
            mx = fmaxf(mx, __shfl_xor_sync(0xffffffffu, mx, 1));
            const float mnew = fmaxf(m_[i], mx);
            const float p0 = __expf(s[i][0] - mnew);
            const float p1 = __expf(s[i][1] - mnew);
            float rs = p0 + p1;
            rs += __shfl_xor_sync(0xffffffffu, rs, 8);
            rs += __shfl_xor_sync(0xffffffffu, rs, 4);
            rs += __shfl_xor_sync(0xffffffffu, rs, 2);
            rs += __shfl_xor_sync(0xffffffffu, rs, 1);
            const float f = __expf(m_[i] - mnew);
            l_[i] = l_[i] * f + rs;
            m_[i] = mnew;
            acc[i][0] *= f; acc[i][1] *= f; acc[i][2] *= f; acc[i][3] *= f;
            *(float2*)&Ps[ty * 4 + i][tx * 2] = make_float2(p0, p1);
        }
        __syncthreads();

#pragma unroll 8
        for (int k = 0; k < 32; ++k) {
            float4 vv = *(const float4*)&Vs[k][tx * 4];
            float p0 = Ps[ty * 4 + 0][k];
            float p1 = Ps[ty * 4 + 1][k];
            float p2 = Ps[ty * 4 + 2][k];
            float p3 = Ps[ty * 4 + 3][k];
            acc[0][0] += p0 * vv.x; acc[0][1] += p0 * vv.y; acc[0][2] += p0 * vv.z; acc[0][3] += p0 * vv.w;
            acc[1][0] += p1 * vv.x; acc[1][1] += p1 * vv.y; acc[1][2] += p1 * vv.z; acc[1][3] += p1 * vv.w;
            acc[2][0] += p2 * vv.x; acc[2][1] += p2 * vv.y; acc[2][2] += p2 * vv.z; acc[2][3] += p2 * vv.w;
            acc[3][0] += p3 * vv.x; acc[3][1] += p3 * vv.y; acc[3][2] += p3 * vv.z; acc[3][3] += p3 * vv.w;
        }
    }

    // Normalize + split-store heads into bf16 hi/lo planes [b*S+s][h*DK+dk]
    const int b = bh >> 4;
    const int h = bh & 15;
#pragma unroll
    for (int i = 0; i < 4; ++i) {
        const float inv = 1.0f / l_[i];
        const size_t row = (size_t)(b * SEQ + q0 + ty * 4 + i);
        const int    col = h * DK + tx * 4;
        float o[4] = {acc[i][0] * inv, acc[i][1] * inv, acc[i][2] * inv, acc[i][3] * inv};
        __nv_bfloat16 hi[4], lo[4];
#pragma unroll
        for (int j = 0; j < 4; ++j) {
            hi[j] = __float2bfloat16_rn(o[j]);
            lo[j] = __float2bfloat16_rn(o[j] - __bfloat162float(hi[j]));
        }
        __nv_bfloat162 h01; h01.x = hi[0]; h01.y = hi[1];
        __nv_bfloat162 h23; h23.x = hi[2]; h23.y = hi[3];
        __nv_bfloat162 l01; l01.x = lo[0]; l01.y = lo[1];
        __nv_bfloat162 l23; l23.x = lo[2]; l23.y = lo[3];
        *(__nv_bfloat162*)(g_hhi + row * DMODEL + col)     = h01;
        *(__nv_bfloat162*)(g_hhi + row * DMODEL + col + 2) = h23;
        *(__nv_bfloat162*)(g_hlo + row * DMODEL + col)     = l01;
        *(__nv_bfloat162*)(g_hlo + row * DMODEL + col + 2) = l23;
    }
}

// ---------------------------------------------------------------------------
extern "C" void kernel_launch(void* const* d_in, const int* in_sizes, int n_in,
                              void* d_out, int out_size)
{
    const float* x     = (const float*)d_in[0];   // [4,2048,1024]
    const float* w_qkv = (const float*)d_in[1];   // [3072,1024]
    const float* w_o   = (const float*)d_in[2];   // [1024,1024]
    float* out = (float*)d_out;                   // [4,2048,1024]

    __nv_bfloat16 *xhi, *xlo, *wqhi, *wqlo, *hhi, *hlo, *wohi, *wolo;
    cudaGetSymbolAddress((void**)&xhi,  g_xhi);
    cudaGetSymbolAddress((void**)&xlo,  g_xlo);
    cudaGetSymbolAddress((void**)&wqhi, g_wqhi);
    cudaGetSymbolAddress((void**)&wqlo, g_wqlo);
    cudaGetSymbolAddress((void**)&hhi,  g_hhi);
    cudaGetSymbolAddress((void**)&hlo,  g_hlo);
    cudaGetSymbolAddress((void**)&wohi, g_wohi);
    cudaGetSymbolAddress((void**)&wolo, g_wolo);

    cudaFuncSetAttribute(gemm_mma_kernel,
                         cudaFuncAttributeMaxDynamicSharedMemorySize, GSMEM);

    // 1) split inputs into bf16 hi/lo planes
    split_kernel<<<NTOK * DMODEL / 4 / 256, 256>>>((const float4*)x, xhi, xlo,
                                                   NTOK * DMODEL / 4);
    split_kernel<<<3 * DMODEL * DMODEL / 4 / 256, 256>>>((const float4*)w_qkv, wqhi, wqlo,
                                                         3 * DMODEL * DMODEL / 4);
    split_kernel<<<DMODEL * DMODEL / 4 / 256, 256>>>((const float4*)w_o, wohi, wolo,
                                                     DMODEL * DMODEL / 4);

    // 2) QKV projection (HMMA split-bf16), scattered into per-head planes
    gemm_mma_kernel<<<dim3(24, 64), 256, GSMEM>>>(xhi, xlo, wqhi, wqlo,
                                                  nullptr, 3 * DMODEL, 1);
    // 3) causal attention (fp32) -> heads hi/lo
    attn_kernel<<<dim3(SEQ / 64, BH), 256>>>();

    // 4) output projection (HMMA split-bf16)
    gemm_mma_kernel<<<dim3(8, 64), 256, GSMEM>>>(hhi, hlo, wohi, wolo,
                                                 out, DMODEL, 0);
}

// round 5
// speedup vs baseline: 2.5832x; 1.7832x over previous
#include <cuda_runtime.h>
#include <cuda_bf16.h>
#include <stdint.h>

// Problem constants
#define BATCH   4
#define HEADS   16
#define SEQ     2048
#define DK      64
#define DMODEL  1024
#define NTOK    (BATCH * SEQ)            // 8192
#define BH      (BATCH * HEADS)          // 64
#define CSTRIDE ((size_t)BH * SEQ * DK)  // elements per Q/K/V plane

// Scratch (device globals: cudaMalloc is forbidden)
__device__ __nv_bfloat16 g_qkvh[3 * BH * SEQ * DK];      // bf16-hi [c][bh][s][dk]
__device__ __nv_bfloat16 g_qkvl[3 * BH * SEQ * DK];      // bf16-lo
__device__ __nv_bfloat16 g_xhi[NTOK * DMODEL];
__device__ __nv_bfloat16 g_xlo[NTOK * DMODEL];
__device__ __nv_bfloat16 g_wqhi[3 * DMODEL * DMODEL];
__device__ __nv_bfloat16 g_wqlo[3 * DMODEL * DMODEL];
__device__ __nv_bfloat16 g_hhi[NTOK * DMODEL];           // attention out hi
__device__ __nv_bfloat16 g_hlo[NTOK * DMODEL];           // attention out lo
__device__ __nv_bfloat16 g_wohi[DMODEL * DMODEL];
__device__ __nv_bfloat16 g_wolo[DMODEL * DMODEL];

// ---------------------------------------------------------------------------
// Warp MMA helpers (sm_80+ instructions only)
// ---------------------------------------------------------------------------
__device__ __forceinline__ uint32_t smem_u32(const void* p) {
    uint32_t a;
    asm("{ .reg .u64 t; cvta.to.shared.u64 t, %1; cvt.u32.u64 %0, t; }"
        : "=r"(a) : "l"(p));
    return a;
}
__device__ __forceinline__ void ldsm_x4(uint32_t& r0, uint32_t& r1,
                                        uint32_t& r2, uint32_t& r3, uint32_t addr) {
    asm volatile("ldmatrix.sync.aligned.m8n8.x4.shared.b16 {%0,%1,%2,%3}, [%4];"
                 : "=r"(r0), "=r"(r1), "=r"(r2), "=r"(r3) : "r"(addr));
}
__device__ __forceinline__ void ldsm_x4t(uint32_t& r0, uint32_t& r1,
                                         uint32_t& r2, uint32_t& r3, uint32_t addr) {
    asm volatile("ldmatrix.sync.aligned.m8n8.x4.trans.shared.b16 {%0,%1,%2,%3}, [%4];"
                 : "=r"(r0), "=r"(r1), "=r"(r2), "=r"(r3) : "r"(addr));
}
__device__ __forceinline__ void ldsm_x2(uint32_t& r0, uint32_t& r1, uint32_t addr) {
    asm volatile("ldmatrix.sync.aligned.m8n8.x2.shared.b16 {%0,%1}, [%2];"
                 : "=r"(r0), "=r"(r1) : "r"(addr));
}
__device__ __forceinline__ void mma_bf16(float* c, const uint32_t* a, const uint32_t* b) {
    asm volatile("mma.sync.aligned.m16n8k16.row.col.f32.bf16.bf16.f32 "
                 "{%0,%1,%2,%3}, {%4,%5,%6,%7}, {%8,%9}, {%0,%1,%2,%3};"
                 : "+f"(c[0]), "+f"(c[1]), "+f"(c[2]), "+f"(c[3])
                 : "r"(a[0]), "r"(a[1]), "r"(a[2]), "r"(a[3]),
                   "r"(b[0]), "r"(b[1]));
}
__device__ __forceinline__ uint32_t pack_bf16(float a, float b) {
    __nv_bfloat162 h;
    h.x = __float2bfloat16_rn(a);
    h.y = __float2bfloat16_rn(b);
    return *(uint32_t*)&h;
}

// ---------------------------------------------------------------------------
// fp32 -> bf16 hi/lo split
// ---------------------------------------------------------------------------
__global__ __launch_bounds__(256)
void split_kernel(const float4* __restrict__ src,
                  __nv_bfloat16* __restrict__ hi,
                  __nv_bfloat16* __restrict__ lo, int n4)
{
    int i = blockIdx.x * blockDim.x + threadIdx.x;
    if (i >= n4) return;
    float4 v = src[i];
    float f[4] = {v.x, v.y, v.z, v.w};
    __nv_bfloat16 h[4], l[4];
#pragma unroll
    for (int j = 0; j < 4; ++j) {
        h[j] = __float2bfloat16_rn(f[j]);
        l[j] = __float2bfloat16_rn(f[j] - __bfloat162float(h[j]));
    }
    __nv_bfloat162 h01; h01.x = h[0]; h01.y = h[1];
    __nv_bfloat162 h23; h23.x = h[2]; h23.y = h[3];
    __nv_bfloat162 l01; l01.x = l[0]; l01.y = l[1];
    __nv_bfloat162 l23; l23.x = l[2]; l23.y = l[3];
    *(__nv_bfloat162*)(hi + 4 * (size_t)i)     = h01;
    *(__nv_bfloat162*)(hi + 4 * (size_t)i + 2) = h23;
    *(__nv_bfloat162*)(lo + 4 * (size_t)i)     = l01;
    *(__nv_bfloat162*)(lo + 4 * (size_t)i + 2) = l23;
}

// ---------------------------------------------------------------------------
// Split-bf16 GEMM on HMMA:  C[M,N] = A[M,K] * B[N,K]^T, K = 1024.
// 128x128 tile, BK=32, 8 warps (2m x 4n), warp tile 64x32.
// mode 0: fp32 store to C.   mode 1: split-store to g_qkvh/g_qkvl planes
// (Q plane pre-scaled by 1/sqrt(DK)).
// ---------------------------------------------------------------------------
#define BKS      32
#define NKI      (DMODEL / BKS)         // 32
#define PLANE_B  (128 * 80)             // 10240 bytes (rows padded to 80 B)
#define STAGE_B4 (4 * PLANE_B)
#define GSMEM    (2 * STAGE_B4)         // 81920 bytes

__global__ __launch_bounds__(256, 1)
void gemm_mma_kernel(const __nv_bfloat16* __restrict__ Ahi,
                     const __nv_bfloat16* __restrict__ Alo,
                     const __nv_bfloat16* __restrict__ Bhi,
                     const __nv_bfloat16* __restrict__ Blo,
                     float* __restrict__ C, int N, int mode)
{
    extern __shared__ char smem[];
    const uint32_t sbase = smem_u32(smem);
    const int tid  = threadIdx.x;
    const int wid  = tid >> 5;
    const int lane = tid & 31;
    const int wm   = wid >> 2;
    const int wn   = wid & 3;
    const int m0   = blockIdx.y * 128;
    const int n0   = blockIdx.x * 128;
    const int K    = DMODEL;

    const __nv_bfloat16* gsrc[4] = {
        Ahi + (size_t)m0 * K, Alo + (size_t)m0 * K,
        Bhi + (size_t)n0 * K, Blo + (size_t)n0 * K };

#pragma unroll
    for (int p = 0; p < 4; ++p)
#pragma unroll
        for (int t = 0; t < 2; ++t) {
            const int idx = tid + t * 256;
            const int r = idx >> 2, c = idx & 3;
            uint4 v = *(const uint4*)(gsrc[p] + (size_t)r * K + c * 8);
            *(uint4*)(smem + p * PLANE_B + r * 80 + c * 16) = v;
        }
    __syncthreads();

    float acc[4][4][4];
#pragma unroll
    for (int mi = 0; mi < 4; ++mi)
#pragma unroll
        for (int nj = 0; nj < 4; ++nj)
#pragma unroll
            for (int q = 0; q < 4; ++q) acc[mi][nj][q] = 0.0f;

    for (int kt = 0; kt < NKI; ++kt) {
        uint4 pf[8];
        if (kt + 1 < NKI) {
            const int kc = (kt + 1) * BKS;
#pragma unroll
            for (int p = 0; p < 4; ++p)
#pragma unroll
                for (int t = 0; t < 2; ++t) {
                    const int idx = tid + t * 256;
                    const int r = idx >> 2, c = idx & 3;
                    pf[p * 2 + t] = *(const uint4*)(gsrc[p] + (size_t)r * K + kc + c * 8);
                }
        }

        const uint32_t sb = sbase + (kt & 1) * STAGE_B4;
#pragma unroll
        for (int ks = 0; ks < 2; ++ks) {
            uint32_t ah[4][4], al[4][4], bh[4][2], bl[4][2];
#pragma unroll
            for (int mi = 0; mi < 4; ++mi) {
                const int row = wm * 64 + mi * 16 + (lane & 15);
                const uint32_t a = sb + row * 80 + ks * 32 + (lane >> 4) * 16;
                ldsm_x4(ah[mi][0], ah[mi][1], ah[mi][2], ah[mi][3], a);
                ldsm_x4(al[mi][0], al[mi][1], al[mi][2], al[mi][3], a + PLANE_B);
            }
#pragma unroll
            for (int nj = 0; nj < 4; ++nj) {
                const int row = wn * 32 + nj * 8 + (lane & 7);
                const uint32_t a = sb + 2 * PLANE_B + row * 80
                                 + ks * 32 + ((lane >> 3) & 1) * 16;
                ldsm_x2(bh[nj][0], bh[nj][1], a);
                ldsm_x2(bl[nj][0], bl[nj][1], a + PLANE_B);
            }
#pragma unroll
            for (int mi = 0; mi < 4; ++mi)
#pragma unroll
                for (int nj = 0; nj < 4; ++nj) {
                    mma_bf16(acc[mi][nj], ah[mi], bh[nj]);
                    mma_bf16(acc[mi][nj], ah[mi], bl[nj]);
                    mma_bf16(acc[mi][nj], al[mi], bh[nj]);
                }
        }

        if (kt + 1 < NKI) {
            __syncthreads();
            char* dst = smem + ((kt + 1) & 1) * STAGE_B4;
#pragma unroll
            for (int p = 0; p < 4; ++p)
#pragma unroll
                for (int t = 0; t < 2; ++t) {
                    const int idx = tid + t * 256;
                    const int r = idx >> 2, c = idx & 3;
                    *(uint4*)(dst + p * PLANE_B + r * 80 + c * 16) = pf[p * 2 + t];
                }
            __syncthreads();
        }
    }

#pragma unroll
    for (int mi = 0; mi < 4; ++mi)
#pragma unroll
        for (int nj = 0; nj < 4; ++nj) {
            const int mrow = m0 + wm * 64 + mi * 16 + (lane >> 2);
            const int ncol = n0 + wn * 32 + nj * 8 + (lane & 3) * 2;
            if (mode == 0) {
                *(float2*)(C + (size_t)mrow * N + ncol) =
                    make_float2(acc[mi][nj][0], acc[mi][nj][1]);
                *(float2*)(C + (size_t)(mrow + 8) * N + ncol) =
                    make_float2(acc[mi][nj][2], acc[mi][nj][3]);
            } else {
                const int cc = ncol >> 10;
                const int h  = (ncol >> 6) & (HEADS - 1);
                const int dk = ncol & (DK - 1);
                const float scl = (cc == 0) ? 0.125f : 1.0f;
#pragma unroll
                for (int half = 0; half < 2; ++half) {
                    const int m = mrow + half * 8;
                    const int b = m >> 11;
                    const int s = m & (SEQ - 1);
                    const size_t off = (size_t)cc * CSTRIDE
                        + ((size_t)(b * HEADS + h) * SEQ + s) * DK + dk;
                    float v0 = acc[mi][nj][half * 2]     * scl;
                    float v1 = acc[mi][nj][half * 2 + 1] * scl;
                    __nv_bfloat162 hi2, lo2;
                    hi2.x = __float2bfloat16_rn(v0);
                    hi2.y = __float2bfloat16_rn(v1);
                    lo2.x = __float2bfloat16_rn(v0 - __bfloat162float(hi2.x));
                    lo2.y = __float2bfloat16_rn(v1 - __bfloat162float(hi2.y));
                    *(__nv_bfloat162*)(g_qkvh + off) = hi2;
                    *(__nv_bfloat162*)(g_qkvl + off) = lo2;
                }
            }
        }
}

// ---------------------------------------------------------------------------
// Causal flash attention on HMMA, split-bf16 (3 MMA terms per product).
// Grid: (SEQ/128, BH). Block: 256 threads = 8 warps; warp owns 16 q-rows.
// KV tiles of 64 keys. FA2 register pipeline: S accum fragments repack to
// P A-fragments; V via ldmatrix.trans.
// ---------------------------------------------------------------------------
#define ASTR   144                    // padded row pitch bytes (64 bf16 + 8 pad)
#define A_QH   0
#define A_QL   (128 * ASTR)
#define A_KH   (2 * 128 * ASTR)
#define A_KL   (A_KH + 64 * ASTR)
#define A_VH   (A_KL + 64 * ASTR)
#define A_VL   (A_VH + 64 * ASTR)
#define A_TOTAL (A_VL + 64 * ASTR)    // 73728 bytes

__global__ __launch_bounds__(256, 1)
void attn_mma_kernel()
{
    extern __shared__ char smem[];
    const uint32_t sb = smem_u32(smem);
    const int tid  = threadIdx.x;
    const int w    = tid >> 5;
    const int lane = tid & 31;
    const int qt   = blockIdx.x;          // 128-row q tile
    const int bh   = blockIdx.y;
    const int q0   = qt * 128;

    const __nv_bfloat16* Qh = g_qkvh + ((size_t)bh * SEQ + q0) * DK;
    const __nv_bfloat16* Ql = g_qkvl + ((size_t)bh * SEQ + q0) * DK;
    const __nv_bfloat16* Kh = g_qkvh + CSTRIDE     + (size_t)bh * SEQ * DK;
    const __nv_bfloat16* Kl = g_qkvl + CSTRIDE     + (size_t)bh * SEQ * DK;
    const __nv_bfloat16* Vh = g_qkvh + 2 * CSTRIDE + (size_t)bh * SEQ * DK;
    const __nv_bfloat16* Vl = g_qkvl + 2 * CSTRIDE + (size_t)bh * SEQ * DK;

    // Load Q tile (128 x 64) hi/lo into smem
    {
        const int r = tid >> 3;
        const int c = tid & 7;
#pragma unroll
        for (int t = 0; t < 4; ++t) {
            const int row = r + t * 32;
            *(uint4*)(smem + A_QH + row * ASTR + c * 16) =
                *(const uint4*)(Qh + (size_t)row * DK + c * 8);
            *(uint4*)(smem + A_QL + row * ASTR + c * 16) =
                *(const uint4*)(Ql + (size_t)row * DK + c * 8);
        }
    }
    __syncthreads();

    // Q fragments (held in registers for entire kernel)
    uint32_t qfh[4][4], qfl[4][4];
#pragma unroll
    for (int kk = 0; kk < 4; ++kk) {
        const int row = w * 16 + (lane & 15);
        const uint32_t a = sb + A_QH + row * ASTR + kk * 32 + (lane >> 4) * 16;
        ldsm_x4(qfh[kk][0], qfh[kk][1], qfh[kk][2], qfh[kk][3], a);
        ldsm_x4(qfl[kk][0], qfl[kk][1], qfl[kk][2], qfl[kk][3],
                a + (A_QL - A_QH));
    }

    float o[8][4];
#pragma unroll
    for (int nj = 0; nj < 8; ++nj)
#pragma unroll
        for (int q = 0; q < 4; ++q) o[nj][q] = 0.0f;
    float mA = -1e30f, mB = -1e30f, lA = 0.0f, lB = 0.0f;

    const int nkt = 2 * qt + 2;
    for (int kt = 0; kt < nkt; ++kt) {
        __syncthreads();
        // Load K/V tiles (64 keys x 64 dk, hi+lo)
        {
            const int r = tid >> 3;
            const int c = tid & 7;
#pragma unroll
            for (int t = 0; t < 2; ++t) {
                const int row = r + t * 32;
                const size_t g = (size_t)(kt * 64 + row) * DK + c * 8;
                const int so = row * ASTR + c * 16;
                *(uint4*)(smem + A_KH + so) = *(const uint4*)(Kh + g);
                *(uint4*)(smem + A_KL + so) = *(const uint4*)(Kl + g);
                *(uint4*)(smem + A_VH + so) = *(const uint4*)(Vh + g);
                *(uint4*)(smem + A_VL + so) = *(const uint4*)(Vl + g);
            }
        }
        __syncthreads();

        // Warps 0-3 (rows q0..q0+63) are fully masked on the last tile
        if (kt == 2 * qt + 1 && w < 4) continue;

        // ---- S = Q K^T (3 terms) ----
        float s[8][4];
#pragma unroll
        for (int nj = 0; nj < 8; ++nj)
#pragma unroll
            for (int q = 0; q < 4; ++q) s[nj][q] = 0.0f;

#pragma unroll
        for (int kk = 0; kk < 4; ++kk) {
            uint32_t bkh[8][2], bkl[8][2];
#pragma unroll
            for (int p2 = 0; p2 < 4; ++p2) {   // nj pair p2 -> nj 2p2, 2p2+1
                const uint32_t a = sb + A_KH + (p2 * 16 + (lane & 15)) * ASTR
                                 + kk * 32 + (lane >> 4) * 16;
                uint32_t r0, r1, r2, r3;
                ldsm_x4(r0, r1, r2, r3, a);
                bkh[2 * p2][0] = r0; bkh[2 * p2][1] = r2;
                bkh[2 * p2 + 1][0] = r1; bkh[2 * p2 + 1][1] = r3;
                ldsm_x4(r0, r1, r2, r3, a + (A_KL - A_KH));
                bkl[2 * p2][0] = r0; bkl[2 * p2][1] = r2;
                bkl[2 * p2 + 1][0] = r1; bkl[2 * p2 + 1][1] = r3;
            }
#pragma unroll
            for (int nj = 0; nj < 8; ++nj) {
                mma_bf16(s[nj], qfh[kk], bkh[nj]);
                mma_bf16(s[nj], qfh[kk], bkl[nj]);
                mma_bf16(s[nj], qfl[kk], bkh[nj]);
            }
        }

        // ---- causal mask (diagonal tiles only) ----
        if (kt >= 2 * qt) {
            const int rowA = q0 + w * 16 + (lane >> 2);
            const int k0   = kt * 64;
#pragma unroll
            for (int nj = 0; nj < 8; ++nj) {
                const int c0 = k0 + nj * 8 + (lane & 3) * 2;
                if (c0 > rowA)     s[nj][0] = -1e30f;
                if (c0 + 1 > rowA) s[nj][1] = -1e30f;
                if (c0 > rowA + 8)     s[nj][2] = -1e30f;
                if (c0 + 1 > rowA + 8) s[nj][3] = -1e30f;
            }
        }

        // ---- online softmax (rows A: lane>>2, B: +8) ----
        float tmA = -1e30f, tmB = -1e30f;
#pragma unroll
        for (int nj = 0; nj < 8; ++nj) {
            tmA = fmaxf(tmA, fmaxf(s[nj][0], s[nj][1]));
            tmB = fmaxf(tmB, fmaxf(s[nj][2], s[nj][3]));
        }
        tmA = fmaxf(tmA, __shfl_xor_sync(0xffffffffu, tmA, 1));
        tmA = fmaxf(tmA, __shfl_xor_sync(0xffffffffu, tmA, 2));
        tmB = fmaxf(tmB, __shfl_xor_sync(0xffffffffu, tmB, 1));
        tmB = fmaxf(tmB, __shfl_xor_sync(0xffffffffu, tmB, 2));
        const float mnA = fmaxf(mA, tmA);
        const float mnB = fmaxf(mB, tmB);
        const float fA = __expf(mA - mnA);
        const float fB = __expf(mB - mnB);
        mA = mnA; mB = mnB;

        float rsA = 0.0f, rsB = 0.0f;
#pragma unroll
        for (int nj = 0; nj < 8; ++nj) {
            s[nj][0] = __expf(s[nj][0] - mnA);
            s[nj][1] = __expf(s[nj][1] - mnA);
            s[nj][2] = __expf(s[nj][2] - mnB);
            s[nj][3] = __expf(s[nj][3] - mnB);
            rsA += s[nj][0] + s[nj][1];
            rsB += s[nj][2] + s[nj][3];
        }
        rsA += __shfl_xor_sync(0xffffffffu, rsA, 1);
        rsA += __shfl_xor_sync(0xffffffffu, rsA, 2);
        rsB += __shfl_xor_sync(0xffffffffu, rsB, 1);
        rsB += __shfl_xor_sync(0xffffffffu, rsB, 2);
        lA = lA * fA + rsA;
        lB = lB * fB + rsB;
#pragma unroll
        for (int nj = 0; nj < 8; ++nj) {
            o[nj][0] *= fA; o[nj][1] *= fA;
            o[nj][2] *= fB; o[nj][3] *= fB;
        }

        // ---- O += P V (3 terms); P hi/lo packed from S fragments ----
#pragma unroll
        for (int kk = 0; kk < 4; ++kk) {
            const int j0 = 2 * kk, j1 = 2 * kk + 1;
            uint32_t ph[4], pl[4];
            ph[0] = pack_bf16(s[j0][0], s[j0][1]);
            ph[1] = pack_bf16(s[j0][2], s[j0][3]);
            ph[2] = pack_bf16(s[j1][0], s[j1][1]);
            ph[3] = pack_bf16(s[j1][2], s[j1][3]);
            {
                __nv_bfloat162* hp;
                float l0, l1;
                hp = (__nv_bfloat162*)&ph[0];
                l0 = s[j0][0] - __bfloat162float(hp->x);
                l1 = s[j0][1] - __bfloat162float(hp->y);
                pl[0] = pack_bf16(l0, l1);
                hp = (__nv_bfloat162*)&ph[1];
                l0 = s[j0][2] - __bfloat162float(hp->x);
                l1 = s[j0][3] - __bfloat162float(hp->y);
                pl[1] = pack_bf16(l0, l1);
                hp = (__nv_bfloat162*)&ph[2];
                l0 = s[j1][0] - __bfloat162float(hp->x);
                l1 = s[j1][1] - __bfloat162float(hp->y);
                pl[2] = pack_bf16(l0, l1);
                hp = (__nv_bfloat162*)&ph[3];
                l0 = s[j1][2] - __bfloat162float(hp->x);
                l1 = s[j1][3] - __bfloat162float(hp->y);
                pl[3] = pack_bf16(l0, l1);
            }
#pragma unroll
            for (int p2 = 0; p2 < 4; ++p2) {   // dk pair -> nj 2p2, 2p2+1
                const uint32_t a = sb + A_VH
                    + (kk * 16 + (lane & 7) + ((lane >> 3) & 1) * 8) * ASTR
                    + p2 * 32 + (lane >> 4) * 16;
                uint32_t r0, r1, r2, r3;
                ldsm_x4t(r0, r1, r2, r3, a);
                uint32_t bvh0[2] = {r0, r1}, bvh1[2] = {r2, r3};
                ldsm_x4t(r0, r1, r2, r3, a + (A_VL - A_VH));
                uint32_t bvl0[2] = {r0, r1}, bvl1[2] = {r2, r3};
                mma_bf16(o[2 * p2],     ph, bvh0);
                mma_bf16(o[2 * p2],     ph, bvl0);
                mma_bf16(o[2 * p2],     pl, bvh0);
                mma_bf16(o[2 * p2 + 1], ph, bvh1);
                mma_bf16(o[2 * p2 + 1], ph, bvl1);
                mma_bf16(o[2 * p2 + 1], pl, bvh1);
            }
        }
    }

    // ---- normalize + split-store heads [b*S+s][h*DK+dk] ----
    const int b = bh >> 4;
    const int h = bh & 15;
    const float iA = 1.0f / lA;
    const float iB = 1.0f / lB;
    const int rowA = q0 + w * 16 + (lane >> 2);
#pragma unroll
    for (int nj = 0; nj < 8; ++nj) {
        const int col = h * DK + nj * 8 + (lane & 3) * 2;
        float v0 = o[nj][0] * iA, v1 = o[nj][1] * iA;
        float v2 = o[nj][2] * iB, v3 = o[nj][3] * iB;
        __nv_bfloat162 hi2, lo2;
        size_t off = (size_t)(b * SEQ + rowA) * DMODEL + col;
        hi2.x = __float2bfloat16_rn(v0);
        hi2.y = __float2bfloat16_rn(v1);
        lo2.x = __float2bfloat16_rn(v0 - __bfloat162float(hi2.x));
        lo2.y = __float2bfloat16_rn(v1 - __bfloat162float(hi2.y));
        *(__nv_bfloat162*)(g_hhi + off) = hi2;
        *(__nv_bfloat162*)(g_hlo + off) = lo2;
        off += 8 * DMODEL;
        hi2.x = __float2bfloat16_rn(v2);
        hi2.y = __float2bfloat16_rn(v3);
        lo2.x = __float2bfloat16_rn(v2 - __bfloat162float(hi2.x));
        lo2.y = __float2bfloat16_rn(v3 - __bfloat162float(hi2.y));
        *(__nv_bfloat162*)(g_hhi + off) = hi2;
        *(__nv_bfloat162*)(g_hlo + off) = lo2;
    }
}

// ---------------------------------------------------------------------------
extern "C" void kernel_launch(void* const* d_in, const int* in_sizes, int n_in,
                              void* d_out, int out_size)
{
    const float* x     = (const float*)d_in[0];
    const float* w_qkv = (const float*)d_in[1];
    const float* w_o   = (const float*)d_in[2];
    float* out = (float*)d_out;

    __nv_bfloat16 *xhi, *xlo, *wqhi, *wqlo, *hhi, *hlo, *wohi, *wolo;
    cudaGetSymbolAddress((void**)&xhi,  g_xhi);
    cudaGetSymbolAddress((void**)&xlo,  g_xlo);
    cudaGetSymbolAddress((void**)&wqhi, g_wqhi);
    cudaGetSymbolAddress((void**)&wqlo, g_wqlo);
    cudaGetSymbolAddress((void**)&hhi,  g_hhi);
    cudaGetSymbolAddress((void**)&hlo,  g_hlo);
    cudaGetSymbolAddress((void**)&wohi, g_wohi);
    cudaGetSymbolAddress((void**)&wolo, g_wolo);

    cudaFuncSetAttribute(gemm_mma_kernel,
                         cudaFuncAttributeMaxDynamicSharedMemorySize, GSMEM);
    cudaFuncSetAttribute(attn_mma_kernel,
                         cudaFuncAttributeMaxDynamicSharedMemorySize, A_TOTAL);

    // 1) split inputs
    split_kernel<<<NTOK * DMODEL / 4 / 256, 256>>>((const float4*)x, xhi, xlo,
                                                   NTOK * DMODEL / 4);
    split_kernel<<<3 * DMODEL * DMODEL / 4 / 256, 256>>>((const float4*)w_qkv, wqhi, wqlo,
                                                         3 * DMODEL * DMODEL / 4);
    split_kernel<<<DMODEL * DMODEL / 4 / 256, 256>>>((const float4*)w_o, wohi, wolo,
                                                     DMODEL * DMODEL / 4);

    // 2) QKV projection -> bf16 hi/lo per-head planes (Q pre-scaled)
    gemm_mma_kernel<<<dim3(24, 64), 256, GSMEM>>>(xhi, xlo, wqhi, wqlo,
                                                  nullptr, 3 * DMODEL, 1);
    // 3) causal flash attention (HMMA split-bf16) -> heads hi/lo
    attn_mma_kernel<<<dim3(SEQ / 128, BH), 256, A_TOTAL>>>();

    // 4) output projection
    gemm_mma_kernel<<<dim3(8, 64), 256, GSMEM>>>(hhi, hlo, wohi, wolo,
                                                 out, DMODEL, 0);
}

// round 6
// speedup vs baseline: 2.6619x; 1.0305x over previous
#include <cuda_runtime.h>
#include <cuda_bf16.h>
#include <stdint.h>

// Problem constants
#define BATCH   4
#define HEADS   16
#define SEQ     2048
#define DK      64
#define DMODEL  1024
#define NTOK    (BATCH * SEQ)            // 8192
#define BH      (BATCH * HEADS)          // 64
#define CSTRIDE ((size_t)BH * SEQ * DK)  // elements per Q/K/V plane

// Scratch (device globals: cudaMalloc is forbidden)
__device__ __nv_bfloat16 g_qkvh[3 * BH * SEQ * DK];      // bf16-hi [c][bh][s][dk]
__device__ __nv_bfloat16 g_qkvl[3 * BH * SEQ * DK];      // bf16-lo
__device__ __nv_bfloat16 g_xhi[NTOK * DMODEL];
__device__ __nv_bfloat16 g_xlo[NTOK * DMODEL];
__device__ __nv_bfloat16 g_wqhi[3 * DMODEL * DMODEL];
__device__ __nv_bfloat16 g_wqlo[3 * DMODEL * DMODEL];
__device__ __nv_bfloat16 g_hhi[NTOK * DMODEL];           // attention out hi
__device__ __nv_bfloat16 g_hlo[NTOK * DMODEL];           // attention out lo
__device__ __nv_bfloat16 g_wohi[DMODEL * DMODEL];
__device__ __nv_bfloat16 g_wolo[DMODEL * DMODEL];

// ---------------------------------------------------------------------------
// Warp MMA + async-copy helpers (sm_80+ instructions only)
// ---------------------------------------------------------------------------
__device__ __forceinline__ uint32_t smem_u32(const void* p) {
    uint32_t a;
    asm("{ .reg .u64 t; cvta.to.shared.u64 t, %1; cvt.u32.u64 %0, t; }"
        : "=r"(a) : "l"(p));
    return a;
}
__device__ __forceinline__ void ldsm_x4(uint32_t& r0, uint32_t& r1,
                                        uint32_t& r2, uint32_t& r3, uint32_t addr) {
    asm volatile("ldmatrix.sync.aligned.m8n8.x4.shared.b16 {%0,%1,%2,%3}, [%4];"
                 : "=r"(r0), "=r"(r1), "=r"(r2), "=r"(r3) : "r"(addr));
}
__device__ __forceinline__ void ldsm_x4t(uint32_t& r0, uint32_t& r1,
                                         uint32_t& r2, uint32_t& r3, uint32_t addr) {
    asm volatile("ldmatrix.sync.aligned.m8n8.x4.trans.shared.b16 {%0,%1,%2,%3}, [%4];"
                 : "=r"(r0), "=r"(r1), "=r"(r2), "=r"(r3) : "r"(addr));
}
__device__ __forceinline__ void ldsm_x2(uint32_t& r0, uint32_t& r1, uint32_t addr) {
    asm volatile("ldmatrix.sync.aligned.m8n8.x2.shared.b16 {%0,%1}, [%2];"
                 : "=r"(r0), "=r"(r1) : "r"(addr));
}
__device__ __forceinline__ void mma_bf16(float* c, const uint32_t* a, const uint32_t* b) {
    asm volatile("mma.sync.aligned.m16n8k16.row.col.f32.bf16.bf16.f32 "
                 "{%0,%1,%2,%3}, {%4,%5,%6,%7}, {%8,%9}, {%0,%1,%2,%3};"
                 : "+f"(c[0]), "+f"(c[1]), "+f"(c[2]), "+f"(c[3])
                 : "r"(a[0]), "r"(a[1]), "r"(a[2]), "r"(a[3]),
                   "r"(b[0]), "r"(b[1]));
}
__device__ __forceinline__ uint32_t pack_bf16(float a, float b) {
    __nv_bfloat162 h;
    h.x = __float2bfloat16_rn(a);
    h.y = __float2bfloat16_rn(b);
    return *(uint32_t*)&h;
}
__device__ __forceinline__ void cp16(uint32_t s, const void* g) {
    asm volatile("cp.async.cg.shared.global [%0], [%1], 16;" :: "r"(s), "l"(g));
}
#define CP_COMMIT() asm volatile("cp.async.commit_group;")
#define CP_WAIT1()  asm volatile("cp.async.wait_group 1;")

// ---------------------------------------------------------------------------
// fp32 -> bf16 hi/lo split
// ---------------------------------------------------------------------------
__global__ __launch_bounds__(256)
void split_kernel(const float4* __restrict__ src,
                  __nv_bfloat16* __restrict__ hi,
                  __nv_bfloat16* __restrict__ lo, int n4)
{
    int i = blockIdx.x * blockDim.x + threadIdx.x;
    if (i >= n4) return;
    float4 v = src[i];
    float f[4] = {v.x, v.y, v.z, v.w};
    __nv_bfloat16 h[4], l[4];
#pragma unroll
    for (int j = 0; j < 4; ++j) {
        h[j] = __float2bfloat16_rn(f[j]);
        l[j] = __float2bfloat16_rn(f[j] - __bfloat162float(h[j]));
    }
    __nv_bfloat162 h01; h01.x = h[0]; h01.y = h[1];
    __nv_bfloat162 h23; h23.x = h[2]; h23.y = h[3];
    __nv_bfloat162 l01; l01.x = l[0]; l01.y = l[1];
    __nv_bfloat162 l23; l23.x = l[2]; l23.y = l[3];
    *(__nv_bfloat162*)(hi + 4 * (size_t)i)     = h01;
    *(__nv_bfloat162*)(hi + 4 * (size_t)i + 2) = h23;
    *(__nv_bfloat162*)(lo + 4 * (size_t)i)     = l01;
    *(__nv_bfloat162*)(lo + 4 * (size_t)i + 2) = l23;
}

// ---------------------------------------------------------------------------
// Split-bf16 GEMM on HMMA with cp.async 2-stage pipeline.
// C[M,N] = A[M,K] * B[N,K]^T, K = 1024. 128x128 tile, BK=32, 8 warps.
// mode 0: fp32 store to C.   mode 1: split-store to g_qkvh/g_qkvl planes
// (Q plane pre-scaled by 1/sqrt(DK)).
// ---------------------------------------------------------------------------
#define BKS      32
#define NKI      (DMODEL / BKS)         // 32
#define PLANE_B  (128 * 80)             // 10240 bytes (rows padded to 80 B)
#define STAGE_B4 (4 * PLANE_B)
#define GSMEM    (2 * STAGE_B4)         // 81920 bytes

__global__ __launch_bounds__(256, 1)
void gemm_mma_kernel(const __nv_bfloat16* __restrict__ Ahi,
                     const __nv_bfloat16* __restrict__ Alo,
                     const __nv_bfloat16* __restrict__ Bhi,
                     const __nv_bfloat16* __restrict__ Blo,
                     float* __restrict__ C, int N, int mode)
{
    extern __shared__ char smem[];
    const uint32_t sbase = smem_u32(smem);
    const int tid  = threadIdx.x;
    const int wid  = tid >> 5;
    const int lane = tid & 31;
    const int wm   = wid >> 2;
    const int wn   = wid & 3;
    const int m0   = blockIdx.y * 128;
    const int n0   = blockIdx.x * 128;
    const int K    = DMODEL;

    const __nv_bfloat16* gsrc[4] = {
        Ahi + (size_t)m0 * K, Alo + (size_t)m0 * K,
        Bhi + (size_t)n0 * K, Blo + (size_t)n0 * K };

    // async stage issue: 8 x 16B per thread
    const int r_  = tid >> 2;
    const int c_  = tid & 3;
    auto issue_stage = [&](int buf, int kc) {
        const uint32_t dst = sbase + buf * STAGE_B4;
#pragma unroll
        for (int p = 0; p < 4; ++p)
#pragma unroll
            for (int t = 0; t < 2; ++t) {
                const int r = r_ + t * 64;
                cp16(dst + p * PLANE_B + r * 80 + c_ * 16,
                     gsrc[p] + (size_t)r * K + kc + c_ * 8);
            }
    };

    issue_stage(0, 0);      CP_COMMIT();
    issue_stage(1, BKS);    CP_COMMIT();

    float acc[4][4][4];
#pragma unroll
    for (int mi = 0; mi < 4; ++mi)
#pragma unroll
        for (int nj = 0; nj < 4; ++nj)
#pragma unroll
            for (int q = 0; q < 4; ++q) acc[mi][nj][q] = 0.0f;

    for (int kt = 0; kt < NKI; ++kt) {
        CP_WAIT1();
        __syncthreads();

        const uint32_t sb = sbase + (kt & 1) * STAGE_B4;
#pragma unroll
        for (int ks = 0; ks < 2; ++ks) {
            uint32_t ah[4][4], al[4][4], bh[4][2], bl[4][2];
#pragma unroll
            for (int mi = 0; mi < 4; ++mi) {
                const int row = wm * 64 + mi * 16 + (lane & 15);
                const uint32_t a = sb + row * 80 + ks * 32 + (lane >> 4) * 16;
                ldsm_x4(ah[mi][0], ah[mi][1], ah[mi][2], ah[mi][3], a);
                ldsm_x4(al[mi][0], al[mi][1], al[mi][2], al[mi][3], a + PLANE_B);
            }
#pragma unroll
            for (int nj = 0; nj < 4; ++nj) {
                const int row = wn * 32 + nj * 8 + (lane & 7);
                const uint32_t a = sb + 2 * PLANE_B + row * 80
                                 + ks * 32 + ((lane >> 3) & 1) * 16;
                ldsm_x2(bh[nj][0], bh[nj][1], a);
                ldsm_x2(bl[nj][0], bl[nj][1], a + PLANE_B);
            }
#pragma unroll
            for (int mi = 0; mi < 4; ++mi)
#pragma unroll
                for (int nj = 0; nj < 4; ++nj) {
                    mma_bf16(acc[mi][nj], ah[mi], bh[nj]);
                    mma_bf16(acc[mi][nj], ah[mi], bl[nj]);
                    mma_bf16(acc[mi][nj], al[mi], bh[nj]);
                }
        }
        __syncthreads();
        if (kt + 2 < NKI) {
            issue_stage(kt & 1, (kt + 2) * BKS);
            CP_COMMIT();
        }
    }

#pragma unroll
    for (int mi = 0; mi < 4; ++mi)
#pragma unroll
        for (int nj = 0; nj < 4; ++nj) {
            const int mrow = m0 + wm * 64 + mi * 16 + (lane >> 2);
            const int ncol = n0 + wn * 32 + nj * 8 + (lane & 3) * 2;
            if (mode == 0) {
                *(float2*)(C + (size_t)mrow * N + ncol) =
                    make_float2(acc[mi][nj][0], acc[mi][nj][1]);
                *(float2*)(C + (size_t)(mrow + 8) * N + ncol) =
                    make_float2(acc[mi][nj][2], acc[mi][nj][3]);
            } else {
                const int cc = ncol >> 10;
                const int h  = (ncol >> 6) & (HEADS - 1);
                const int dk = ncol & (DK - 1);
                const float scl = (cc == 0) ? 0.125f : 1.0f;
#pragma unroll
                for (int half = 0; half < 2; ++half) {
                    const int m = mrow + half * 8;
                    const int b = m >> 11;
                    const int s = m & (SEQ - 1);
                    const size_t off = (size_t)cc * CSTRIDE
                        + ((size_t)(b * HEADS + h) * SEQ + s) * DK + dk;
                    float v0 = acc[mi][nj][half * 2]     * scl;
                    float v1 = acc[mi][nj][half * 2 + 1] * scl;
                    __nv_bfloat162 hi2, lo2;
                    hi2.x = __float2bfloat16_rn(v0);
                    hi2.y = __float2bfloat16_rn(v1);
                    lo2.x = __float2bfloat16_rn(v0 - __bfloat162float(hi2.x));
                    lo2.y = __float2bfloat16_rn(v1 - __bfloat162float(hi2.y));
                    *(__nv_bfloat162*)(g_qkvh + off) = hi2;
                    *(__nv_bfloat162*)(g_qkvl + off) = lo2;
                }
            }
        }
}

// ---------------------------------------------------------------------------
// Causal flash attention on HMMA, split-bf16 (3 MMA terms per product).
// Grid: (SEQ/128, BH). Block: 256 threads = 8 warps; warp owns 16 q-rows.
// KV tiles of 64 keys; next tile register-prefetched during compute.
// ---------------------------------------------------------------------------
#define ASTR   144                    // padded row pitch bytes (64 bf16 + 8 pad)
#define A_QH   0
#define A_QL   (128 * ASTR)
#define A_KH   (2 * 128 * ASTR)
#define A_KL   (A_KH + 64 * ASTR)
#define A_VH   (A_KL + 64 * ASTR)
#define A_VL   (A_VH + 64 * ASTR)
#define A_TOTAL (A_VL + 64 * ASTR)    // 73728 bytes

__global__ __launch_bounds__(256, 1)
void attn_mma_kernel()
{
    extern __shared__ char smem[];
    const uint32_t sb = smem_u32(smem);
    const int tid  = threadIdx.x;
    const int w    = tid >> 5;
    const int lane = tid & 31;
    const int qt   = blockIdx.x;          // 128-row q tile
    const int bh   = blockIdx.y;
    const int q0   = qt * 128;

    const __nv_bfloat16* Qh = g_qkvh + ((size_t)bh * SEQ + q0) * DK;
    const __nv_bfloat16* Ql = g_qkvl + ((size_t)bh * SEQ + q0) * DK;
    const __nv_bfloat16* Kh = g_qkvh + CSTRIDE     + (size_t)bh * SEQ * DK;
    const __nv_bfloat16* Kl = g_qkvl + CSTRIDE     + (size_t)bh * SEQ * DK;
    const __nv_bfloat16* Vh = g_qkvh + 2 * CSTRIDE + (size_t)bh * SEQ * DK;
    const __nv_bfloat16* Vl = g_qkvl + 2 * CSTRIDE + (size_t)bh * SEQ * DK;

    const int r_ = tid >> 3;              // 0..31
    const int c_ = tid & 7;               // 16B chunk

    // Load Q tile (128 x 64) hi/lo + KV tile 0 into smem
#pragma unroll
    for (int t = 0; t < 4; ++t) {
        const int row = r_ + t * 32;
        *(uint4*)(smem + A_QH + row * ASTR + c_ * 16) =
            *(const uint4*)(Qh + (size_t)row * DK + c_ * 8);
        *(uint4*)(smem + A_QL + row * ASTR + c_ * 16) =
            *(const uint4*)(Ql + (size_t)row * DK + c_ * 8);
    }
#pragma unroll
    for (int t = 0; t < 2; ++t) {
        const int row = r_ + t * 32;
        const size_t g = (size_t)row * DK + c_ * 8;
        const int so = row * ASTR + c_ * 16;
        *(uint4*)(smem + A_KH + so) = *(const uint4*)(Kh + g);
        *(uint4*)(smem + A_KL + so) = *(const uint4*)(Kl + g);
        *(uint4*)(smem + A_VH + so) = *(const uint4*)(Vh + g);
        *(uint4*)(smem + A_VL + so) = *(const uint4*)(Vl + g);
    }
    __syncthreads();

    // Q fragments (registers, whole kernel)
    uint32_t qfh[4][4], qfl[4][4];
#pragma unroll
    for (int kk = 0; kk < 4; ++kk) {
        const int row = w * 16 + (lane & 15);
        const uint32_t a = sb + A_QH + row * ASTR + kk * 32 + (lane >> 4) * 16;
        ldsm_x4(qfh[kk][0], qfh[kk][1], qfh[kk][2], qfh[kk][3], a);
        ldsm_x4(qfl[kk][0], qfl[kk][1], qfl[kk][2], qfl[kk][3],
                a + (A_QL - A_QH));
    }

    float o[8][4];
#pragma unroll
    for (int nj = 0; nj < 8; ++nj)
#pragma unroll
        for (int q = 0; q < 4; ++q) o[nj][q] = 0.0f;
    float mA = -1e30f, mB = -1e30f, lA = 0.0f, lB = 0.0f;

    const int nkt = 2 * qt + 2;
    for (int kt = 0; kt < nkt; ++kt) {
        // Prefetch next KV tile into registers (latency hidden by compute)
        uint4 pf[8];
        const bool havepf = (kt + 1 < nkt);
        if (havepf) {
#pragma unroll
            for (int t = 0; t < 2; ++t) {
                const int row = r_ + t * 32;
                const size_t g = (size_t)((kt + 1) * 64 + row) * DK + c_ * 8;
                pf[t * 4 + 0] = *(const uint4*)(Kh + g);
                pf[t * 4 + 1] = *(const uint4*)(Kl + g);
                pf[t * 4 + 2] = *(const uint4*)(Vh + g);
                pf[t * 4 + 3] = *(const uint4*)(Vl + g);
            }
        }

        // Warps 0-3 (rows q0..q0+63) fully masked on the last diagonal tile
        if (!(kt == 2 * qt + 1 && w < 4)) {
            // ---- S = Q K^T (3 terms) ----
            float s[8][4];
#pragma unroll
            for (int nj = 0; nj < 8; ++nj)
#pragma unroll
                for (int q = 0; q < 4; ++q) s[nj][q] = 0.0f;

#pragma unroll
            for (int kk = 0; kk < 4; ++kk) {
                uint32_t bkh[8][2], bkl[8][2];
#pragma unroll
                for (int p2 = 0; p2 < 4; ++p2) {
                    const uint32_t a = sb + A_KH + (p2 * 16 + (lane & 15)) * ASTR
                                     + kk * 32 + (lane >> 4) * 16;
                    uint32_t r0, r1, r2, r3;
                    ldsm_x4(r0, r1, r2, r3, a);
                    bkh[2 * p2][0] = r0; bkh[2 * p2][1] = r2;
                    bkh[2 * p2 + 1][0] = r1; bkh[2 * p2 + 1][1] = r3;
                    ldsm_x4(r0, r1, r2, r3, a + (A_KL - A_KH));
                    bkl[2 * p2][0] = r0; bkl[2 * p2][1] = r2;
                    bkl[2 * p2 + 1][0] = r1; bkl[2 * p2 + 1][1] = r3;
                }
#pragma unroll
                for (int nj = 0; nj < 8; ++nj) {
                    mma_bf16(s[nj], qfh[kk], bkh[nj]);
                    mma_bf16(s[nj], qfh[kk], bkl[nj]);
                    mma_bf16(s[nj], qfl[kk], bkh[nj]);
                }
            }

            // ---- causal mask (diagonal tiles only) ----
            if (kt >= 2 * qt) {
                const int rowA = q0 + w * 16 + (lane >> 2);
                const int k0   = kt * 64;
#pragma unroll
                for (int nj = 0; nj < 8; ++nj) {
                    const int c0 = k0 + nj * 8 + (lane & 3) * 2;
                    if (c0 > rowA)     s[nj][0] = -1e30f;
                    if (c0 + 1 > rowA) s[nj][1] = -1e30f;
                    if (c0 > rowA + 8)     s[nj][2] = -1e30f;
                    if (c0 + 1 > rowA + 8) s[nj][3] = -1e30f;
                }
            }

            // ---- online softmax ----
            float tmA = -1e30f, tmB = -1e30f;
#pragma unroll
            for (int nj = 0; nj < 8; ++nj) {
                tmA = fmaxf(tmA, fmaxf(s[nj][0], s[nj][1]));
                tmB = fmaxf(tmB, fmaxf(s[nj][2], s[nj][3]));
            }
            tmA = fmaxf(tmA, __shfl_xor_sync(0xffffffffu, tmA, 1));
            tmA = fmaxf(tmA, __shfl_xor_sync(0xffffffffu, tmA, 2));
            tmB = fmaxf(tmB, __shfl_xor_sync(0xffffffffu, tmB, 1));
            tmB = fmaxf(tmB, __shfl_xor_sync(0xffffffffu, tmB, 2));
            const float mnA = fmaxf(mA, tmA);
            const float mnB = fmaxf(mB, tmB);
            const float fA = __expf(mA - mnA);
            const float fB = __expf(mB - mnB);
            mA = mnA; mB = mnB;

            float rsA = 0.0f, rsB = 0.0f;
#pragma unroll
            for (int nj = 0; nj < 8; ++nj) {
                s[nj][0] = __expf(s[nj][0] - mnA);
                s[nj][1] = __expf(s[nj][1] - mnA);
                s[nj][2] = __expf(s[nj][2] - mnB);
                s[nj][3] = __expf(s[nj][3] - mnB);
                rsA += s[nj][0] + s[nj][1];
                rsB += s[nj][2] + s[nj][3];
            }
            rsA += __shfl_xor_sync(0xffffffffu, rsA, 1);
            rsA += __shfl_xor_sync(0xffffffffu, rsA, 2);
            rsB += __shfl_xor_sync(0xffffffffu, rsB, 1);
            rsB += __shfl_xor_sync(0xffffffffu, rsB, 2);
            lA = lA * fA + rsA;
            lB = lB * fB + rsB;
#pragma unroll
            for (int nj = 0; nj < 8; ++nj) {
                o[nj][0] *= fA; o[nj][1] *= fA;
                o[nj][2] *= fB; o[nj][3] *= fB;
            }

            // ---- O += P V (3 terms) ----
#pragma unroll
            for (int kk = 0; kk < 4; ++kk) {
                const int j0 = 2 * kk, j1 = 2 * kk + 1;
                uint32_t ph[4], pl[4];
                ph[0] = pack_bf16(s[j0][0], s[j0][1]);
                ph[1] = pack_bf16(s[j0][2], s[j0][3]);
                ph[2] = pack_bf16(s[j1][0], s[j1][1]);
                ph[3] = pack_bf16(s[j1][2], s[j1][3]);
                {
                    __nv_bfloat162* hp;
                    float l0, l1;
                    hp = (__nv_bfloat162*)&ph[0];
                    l0 = s[j0][0] - __bfloat162float(hp->x);
                    l1 = s[j0][1] - __bfloat162float(hp->y);
                    pl[0] = pack_bf16(l0, l1);
                    hp = (__nv_bfloat162*)&ph[1];
                    l0 = s[j0][2] - __bfloat162float(hp->x);
                    l1 = s[j0][3] - __bfloat162float(hp->y);
                    pl[1] = pack_bf16(l0, l1);
                    hp = (__nv_bfloat162*)&ph[2];
                    l0 = s[j1][0] - __bfloat162float(hp->x);
                    l1 = s[j1][1] - __bfloat162float(hp->y);
                    pl[2] = pack_bf16(l0, l1);
                    hp = (__nv_bfloat162*)&ph[3];
                    l0 = s[j1][2] - __bfloat162float(hp->x);
                    l1 = s[j1][3] - __bfloat162float(hp->y);
                    pl[3] = pack_bf16(l0, l1);
                }
#pragma unroll
                for (int p2 = 0; p2 < 4; ++p2) {
                    const uint32_t a = sb + A_VH
                        + (kk * 16 + (lane & 7) + ((lane >> 3) & 1) * 8) * ASTR
                        + p2 * 32 + (lane >> 4) * 16;
                    uint32_t r0, r1, r2, r3;
                    ldsm_x4t(r0, r1, r2, r3, a);
                    uint32_t bvh0[2] = {r0, r1}, bvh1[2] = {r2, r3};
                    ldsm_x4t(r0, r1, r2, r3, a + (A_VL - A_VH));
                    uint32_t bvl0[2] = {r0, r1}, bvl1[2] = {r2, r3};
                    mma_bf16(o[2 * p2],     ph, bvh0);
                    mma_bf16(o[2 * p2],     ph, bvl0);
                    mma_bf16(o[2 * p2],     pl, bvh0);
                    mma_bf16(o[2 * p2 + 1], ph, bvh1);
                    mma_bf16(o[2 * p2 + 1], ph, bvl1);
                    mma_bf16(o[2 * p2 + 1], pl, bvh1);
                }
            }
        }

        if (havepf) {
            __syncthreads();   // all warps done reading current KV tile
#pragma unroll
            for (int t = 0; t < 2; ++t) {
                const int row = r_ + t * 32;
                const int so = row * ASTR + c_ * 16;
                *(uint4*)(smem + A_KH + so) = pf[t * 4 + 0];
                *(uint4*)(smem + A_KL + so) = pf[t * 4 + 1];
                *(uint4*)(smem + A_VH + so) = pf[t * 4 + 2];
                *(uint4*)(smem + A_VL + so) = pf[t * 4 + 3];
            }
            __syncthreads();
        }
    }

    // ---- normalize + split-store heads [b*S+s][h*DK+dk] ----
    const int b = bh >> 4;
    const int h = bh & 15;
    const float iA = 1.0f / lA;
    const float iB = 1.0f / lB;
    const int rowA = q0 + w * 16 + (lane >> 2);
#pragma unroll
    for (int nj = 0; nj < 8; ++nj) {
        const int col = h * DK + nj * 8 + (lane & 3) * 2;
        float v0 = o[nj][0] * iA, v1 = o[nj][1] * iA;
        float v2 = o[nj][2] * iB, v3 = o[nj][3] * iB;
        __nv_bfloat162 hi2, lo2;
        size_t off = (size_t)(b * SEQ + rowA) * DMODEL + col;
        hi2.x = __float2bfloat16_rn(v0);
        hi2.y = __float2bfloat16_rn(v1);
        lo2.x = __float2bfloat16_rn(v0 - __bfloat162float(hi2.x));
        lo2.y = __float2bfloat16_rn(v1 - __bfloat162float(hi2.y));
        *(__nv_bfloat162*)(g_hhi + off) = hi2;
        *(__nv_bfloat162*)(g_hlo + off) = lo2;
        off += 8 * DMODEL;
        hi2.x = __float2bfloat16_rn(v2);
        hi2.y = __float2bfloat16_rn(v3);
        lo2.x = __float2bfloat16_rn(v2 - __bfloat162float(hi2.x));
        lo2.y = __float2bfloat16_rn(v3 - __bfloat162float(hi2.y));
        *(__nv_bfloat162*)(g_hhi + off) = hi2;
        *(__nv_bfloat162*)(g_hlo + off) = lo2;
    }
}

// ---------------------------------------------------------------------------
extern "C" void kernel_launch(void* const* d_in, const int* in_sizes, int n_in,
                              void* d_out, int out_size)
{
    const float* x     = (const float*)d_in[0];
    const float* w_qkv = (const float*)d_in[1];
    const float* w_o   = (const float*)d_in[2];
    float* out = (float*)d_out;

    __nv_bfloat16 *xhi, *xlo, *wqhi, *wqlo, *hhi, *hlo, *wohi, *wolo;
    cudaGetSymbolAddress((void**)&xhi,  g_xhi);
    cudaGetSymbolAddress((void**)&xlo,  g_xlo);
    cudaGetSymbolAddress((void**)&wqhi, g_wqhi);
    cudaGetSymbolAddress((void**)&wqlo, g_wqlo);
    cudaGetSymbolAddress((void**)&hhi,  g_hhi);
    cudaGetSymbolAddress((void**)&hlo,  g_hlo);
    cudaGetSymbolAddress((void**)&wohi, g_wohi);
    cudaGetSymbolAddress((void**)&wolo, g_wolo);

    cudaFuncSetAttribute(gemm_mma_kernel,
                         cudaFuncAttributeMaxDynamicSharedMemorySize, GSMEM);
    cudaFuncSetAttribute(attn_mma_kernel,
                         cudaFuncAttributeMaxDynamicSharedMemorySize, A_TOTAL);

    // 1) split inputs
    split_kernel<<<NTOK * DMODEL / 4 / 256, 256>>>((const float4*)x, xhi, xlo,
                                                   NTOK * DMODEL / 4);
    split_kernel<<<3 * DMODEL * DMODEL / 4 / 256, 256>>>((const float4*)w_qkv, wqhi, wqlo,
                                                         3 * DMODEL * DMODEL / 4);
    split_kernel<<<DMODEL * DMODEL / 4 / 256, 256>>>((const float4*)w_o, wohi, wolo,
                                                     DMODEL * DMODEL / 4);

    // 2) QKV projection -> bf16 hi/lo per-head planes (Q pre-scaled)
    gemm_mma_kernel<<<dim3(24, 64), 256, GSMEM>>>(xhi, xlo, wqhi, wqlo,
                                                  nullptr, 3 * DMODEL, 1);
    // 3) causal flash attention (HMMA split-bf16) -> heads hi/lo
    attn_mma_kernel<<<dim3(SEQ / 128, BH), 256, A_TOTAL>>>();

    // 4) output projection
    gemm_mma_kernel<<<dim3(8, 64), 256, GSMEM>>>(hhi, hlo, wohi, wolo,
                                                 out, DMODEL, 0);
}